// round 7
// baseline (speedup 1.0000x reference)
#include <cuda_runtime.h>
#include <cuda_bf16.h>

// Batched antialiased bilinear resize (128,96) -> (32,24), scale 1/4.
// Separable triangle filter, support 4: output o samples s=4o+1.5, taps
// j=4o-2..4o+5, raw weights {1,3,5,7,7,5,3,1}/8, normalized by the in-range
// tap sum (4.0 interior, 3.5 at first/last output).
//
// Fully warp-synchronous: NO shared memory, NO barriers.
// Warp w owns output rows 4w..4w+3, reading input rows 16w-2..16w+17.
// Lane oc (0..23) holds the float4 of columns 4oc..4oc+3; horizontal 8-tap
// done with 4 warp shuffles at emit time. Four accumulators + a 6-deep
// explicit load pipeline (independent LDG.128s in flight through the emit
// phases). Streaming cache hints (__ldcs/__stcs): data has no reuse beyond
// the 2-row warp overlap, which L1 covers.
// Edge bounds checks exist only in the w==0 / w==7 template paths.

#define BB   2048
#define CC   6
#define HH   128
#define WW   96
#define OH   32
#define OW   24

#define PIPE 6

__device__ __forceinline__ float4 f4zero() { return make_float4(0.f, 0.f, 0.f, 0.f); }

template<bool LO, bool HI>
__device__ __forceinline__ void strip(const float* __restrict__ src,
                                      float* __restrict__ dst,
                                      int w, int lane, float hn) {
    constexpr float WT[8] = {0.125f, 0.375f, 0.625f, 0.875f,
                             0.875f, 0.625f, 0.375f, 0.125f};
    constexpr float QTR  = 0.25f;
    constexpr float EDGE = 1.0f / 3.5f;

    const int rbase = 16 * w - 2;

    // streaming row load: only LO path can see r<0 (jl<2), only HI path r>=HH (jl>=18)
    auto loadrow = [&](int jl) -> float4 {
        const int r = rbase + jl;
        if (LO && jl < 2   && r < 0)   return f4zero();
        if (HI && jl >= 18 && r >= HH) return f4zero();
        return __ldcs((const float4*)(src + r * WW));
    };

    // horizontal filter + store one vertically-filtered output row
    auto emit = [&](float4 a, int oh, float vn) {
        float lz = __shfl_up_sync  (0xFFFFFFFFu, a.z, 1);
        float lw = __shfl_up_sync  (0xFFFFFFFFu, a.w, 1);
        float rx = __shfl_down_sync(0xFFFFFFFFu, a.x, 1);
        float ry = __shfl_down_sync(0xFFFFFFFFu, a.y, 1);
        if (lane == 0)      { lz = 0.f; lw = 0.f; }
        if (lane == OW - 1) { rx = 0.f; ry = 0.f; }
        float res = 0.125f * lz + 0.375f * lw
                  + 0.625f * a.x + 0.875f * a.y + 0.875f * a.z + 0.625f * a.w
                  + 0.375f * rx + 0.125f * ry;
        if (lane < OW)
            __stcs(dst + oh * OW + lane, res * (vn * hn));
    };

    const float vn0 = LO ? EDGE : QTR;   // oh = 4w   (edge renorm only at oh=0)
    const float vn3 = HI ? EDGE : QTR;   // oh = 4w+3 (edge renorm only at oh=31)

    // PIPE-deep software pipeline (ring indexed &7; slots beyond PIPE unused)
    float4 vbuf[8];
    #pragma unroll
    for (int p = 0; p < PIPE; p++) vbuf[p & 7] = loadrow(p);

    float4 A0 = f4zero(), A1 = f4zero(), A2 = f4zero(), A3 = f4zero();

    #pragma unroll
    for (int jl = 0; jl < 20; jl++) {
        float4 v = vbuf[jl & 7];
        if (jl + PIPE < 20) vbuf[(jl + PIPE) & 7] = loadrow(jl + PIPE);

        if (jl <= 7) {
            const float c = WT[jl];
            A0.x += c * v.x; A0.y += c * v.y; A0.z += c * v.z; A0.w += c * v.w;
        }
        if (jl >= 4 && jl <= 11) {
            const float c = WT[jl - 4];
            A1.x += c * v.x; A1.y += c * v.y; A1.z += c * v.z; A1.w += c * v.w;
        }
        if (jl >= 8 && jl <= 15) {
            const float c = WT[jl - 8];
            A2.x += c * v.x; A2.y += c * v.y; A2.z += c * v.z; A2.w += c * v.w;
        }
        if (jl >= 12) {
            const float c = WT[jl - 12];
            A3.x += c * v.x; A3.y += c * v.y; A3.z += c * v.z; A3.w += c * v.w;
        }

        if (jl == 7)  emit(A0, 4 * w + 0, vn0);
        if (jl == 11) emit(A1, 4 * w + 1, QTR);
        if (jl == 15) emit(A2, 4 * w + 2, QTR);
        if (jl == 19) emit(A3, 4 * w + 3, vn3);
    }
}

__global__ __launch_bounds__(256)
void resize_aa_kernel(const float* __restrict__ x, float* __restrict__ out) {
    const int img  = blockIdx.x;            // 0 .. B*C-1
    const int tid  = threadIdx.x;
    const int w    = tid >> 5;              // warp 0..7 -> output rows 4w..4w+3
    const int lane = tid & 31;
    const int oc   = (lane < OW) ? lane : (OW - 1);  // lanes 24..31 shadow 23

    const float* __restrict__ src = x + (size_t)img * (HH * WW) + 4 * oc;
    float* __restrict__ dst = out + (size_t)img * (OH * OW);

    const float hn = (oc == 0 || oc == OW - 1) ? (1.0f / 3.5f) : 0.25f;

    if (w == 0)       strip<true,  false>(src, dst, w, lane, hn);
    else if (w == 7)  strip<false, true >(src, dst, w, lane, hn);
    else              strip<false, false>(src, dst, w, lane, hn);
}

extern "C" void kernel_launch(void* const* d_in, const int* in_sizes, int n_in,
                              void* d_out, int out_size) {
    const float* x = (const float*)d_in[0];   // (2048, 6, 128, 96) float32
    float* out = (float*)d_out;               // (2048, 6, 768) float32
    resize_aa_kernel<<<BB * CC, 256>>>(x, out);
}

// round 8
// speedup vs baseline: 1.0179x; 1.0179x over previous
#include <cuda_runtime.h>
#include <cuda_bf16.h>

// Batched antialiased bilinear resize (128,96) -> (32,24), scale 1/4.
// Separable triangle filter, support 4: output o samples s=4o+1.5, taps
// j=4o-2..4o+5, raw weights {1,3,5,7,7,5,3,1}/8, normalized by the in-range
// tap sum (4.0 interior, 3.5 at first/last output).
//
// Fully warp-synchronous: NO shared memory, NO barriers.
// Warp w owns output rows 4w..4w+3, reading input rows 16w-2..16w+17.
// Lane oc (0..23) holds the float4 of columns 4oc..4oc+3; horizontal 8-tap
// done with 4 warp shuffles at emit time. Four accumulators + a 4-deep
// explicit load pipeline (R6 best config: regs ~44, 5 CTAs/SM). This round
// adds ONLY streaming cache hints (__ldcs/__stcs) on top of R6 — the data is
// single-touch, so evict-first policy cuts L2 replacement interference.
// Edge bounds checks exist only in the w==0 / w==7 template paths.

#define BB   2048
#define CC   6
#define HH   128
#define WW   96
#define OH   32
#define OW   24

#define PIPE 4

__device__ __forceinline__ float4 f4zero() { return make_float4(0.f, 0.f, 0.f, 0.f); }

template<bool LO, bool HI>
__device__ __forceinline__ void strip(const float* __restrict__ src,
                                      float* __restrict__ dst,
                                      int w, int lane, float hn) {
    constexpr float WT[8] = {0.125f, 0.375f, 0.625f, 0.875f,
                             0.875f, 0.625f, 0.375f, 0.125f};
    constexpr float QTR  = 0.25f;
    constexpr float EDGE = 1.0f / 3.5f;

    const int rbase = 16 * w - 2;

    // streaming row load: only LO path can see r<0 (jl<2), only HI path r>=HH (jl>=18)
    auto loadrow = [&](int jl) -> float4 {
        const int r = rbase + jl;
        if (LO && jl < 2   && r < 0)   return f4zero();
        if (HI && jl >= 18 && r >= HH) return f4zero();
        return __ldcs((const float4*)(src + r * WW));
    };

    // horizontal filter + store one vertically-filtered output row
    auto emit = [&](float4 a, int oh, float vn) {
        float lz = __shfl_up_sync  (0xFFFFFFFFu, a.z, 1);
        float lw = __shfl_up_sync  (0xFFFFFFFFu, a.w, 1);
        float rx = __shfl_down_sync(0xFFFFFFFFu, a.x, 1);
        float ry = __shfl_down_sync(0xFFFFFFFFu, a.y, 1);
        if (lane == 0)      { lz = 0.f; lw = 0.f; }
        if (lane == OW - 1) { rx = 0.f; ry = 0.f; }
        float res = 0.125f * lz + 0.375f * lw
                  + 0.625f * a.x + 0.875f * a.y + 0.875f * a.z + 0.625f * a.w
                  + 0.375f * rx + 0.125f * ry;
        if (lane < OW)
            __stcs(dst + oh * OW + lane, res * (vn * hn));
    };

    const float vn0 = LO ? EDGE : QTR;   // oh = 4w   (edge renorm only at oh=0)
    const float vn3 = HI ? EDGE : QTR;   // oh = 4w+3 (edge renorm only at oh=31)

    // 4-deep software pipeline
    float4 vbuf[PIPE];
    #pragma unroll
    for (int p = 0; p < PIPE; p++) vbuf[p] = loadrow(p);

    float4 A0 = f4zero(), A1 = f4zero(), A2 = f4zero(), A3 = f4zero();

    #pragma unroll
    for (int jl = 0; jl < 20; jl++) {
        float4 v = vbuf[jl % PIPE];
        if (jl + PIPE < 20) vbuf[jl % PIPE] = loadrow(jl + PIPE);

        if (jl <= 7) {
            const float c = WT[jl];
            A0.x += c * v.x; A0.y += c * v.y; A0.z += c * v.z; A0.w += c * v.w;
        }
        if (jl >= 4 && jl <= 11) {
            const float c = WT[jl - 4];
            A1.x += c * v.x; A1.y += c * v.y; A1.z += c * v.z; A1.w += c * v.w;
        }
        if (jl >= 8 && jl <= 15) {
            const float c = WT[jl - 8];
            A2.x += c * v.x; A2.y += c * v.y; A2.z += c * v.z; A2.w += c * v.w;
        }
        if (jl >= 12) {
            const float c = WT[jl - 12];
            A3.x += c * v.x; A3.y += c * v.y; A3.z += c * v.z; A3.w += c * v.w;
        }

        if (jl == 7)  emit(A0, 4 * w + 0, vn0);
        if (jl == 11) emit(A1, 4 * w + 1, QTR);
        if (jl == 15) emit(A2, 4 * w + 2, QTR);
        if (jl == 19) emit(A3, 4 * w + 3, vn3);
    }
}

__global__ __launch_bounds__(256)
void resize_aa_kernel(const float* __restrict__ x, float* __restrict__ out) {
    const int img  = blockIdx.x;            // 0 .. B*C-1
    const int tid  = threadIdx.x;
    const int w    = tid >> 5;              // warp 0..7 -> output rows 4w..4w+3
    const int lane = tid & 31;
    const int oc   = (lane < OW) ? lane : (OW - 1);  // lanes 24..31 shadow 23

    const float* __restrict__ src = x + (size_t)img * (HH * WW) + 4 * oc;
    float* __restrict__ dst = out + (size_t)img * (OH * OW);

    const float hn = (oc == 0 || oc == OW - 1) ? (1.0f / 3.5f) : 0.25f;

    if (w == 0)       strip<true,  false>(src, dst, w, lane, hn);
    else if (w == 7)  strip<false, true >(src, dst, w, lane, hn);
    else              strip<false, false>(src, dst, w, lane, hn);
}

extern "C" void kernel_launch(void* const* d_in, const int* in_sizes, int n_in,
                              void* d_out, int out_size) {
    const float* x = (const float*)d_in[0];   // (2048, 6, 128, 96) float32
    float* out = (float*)d_out;               // (2048, 6, 768) float32
    resize_aa_kernel<<<BB * CC, 256>>>(x, out);
}